// round 1
// baseline (speedup 1.0000x reference)
#include <cuda_runtime.h>

// Problem dims
constexpr int VOCAB = 50257;
constexpr int DIM   = 50;
constexpr int NU1   = 32;   // GRU1 units, 3*NU1 = 96
constexpr int NU2   = 64;   // GRU2 units, 3*NU2 = 192
constexpr int NB    = 1024;
constexpr int NT    = 1024;

constexpr int KH1_STRIDE = 97;   // pad 96 -> 97 so bank = (j + c) % 32 (conflict-free)
constexpr int KX2_STRIDE = 193;  // pad 192 -> 193
constexpr int KH2_STRIDE = 193;

// Precomputed embedding projection: embproj[v][k] = sum_d emb[v][d]*kx1[d][k] + b1[0][k]
// 50257 * 96 floats = 19.3 MB -> lives in L2 during the recurrent kernel.
__device__ float g_embproj[(size_t)VOCAB * 96];

__device__ __forceinline__ float sigf(float x) {
    return __fdividef(1.0f, 1.0f + __expf(-x));
}
__device__ __forceinline__ float tanh_fast(float x) {
    // tanh(x) = 1 - 2/(exp(2x)+1); saturates correctly at +-inf
    return 1.0f - __fdividef(2.0f, 1.0f + __expf(2.0f * x));
}

// ---------------------------------------------------------------------------
// Kernel A: embproj = emb @ kx1 + b1[0]   ([V,50] x [50,96] -> [V,96])
// ---------------------------------------------------------------------------
__global__ void __launch_bounds__(96) embproj_kernel(const float* __restrict__ emb,
                                                     const float* __restrict__ kx1,
                                                     const float* __restrict__ b1) {
    __shared__ float kx1s[DIM * 96];
    __shared__ float xrow[DIM];
    const int tid = threadIdx.x;  // 96 threads, one per output column
    for (int i = tid; i < DIM * 96; i += 96) kx1s[i] = kx1[i];
    const float bc = b1[tid];  // b1[0][tid]
    __syncthreads();

    const int row0 = blockIdx.x * 16;
    for (int k = 0; k < 16; k++) {
        const int row = row0 + k;
        if (row >= VOCAB) break;
        if (tid < DIM) xrow[tid] = emb[(size_t)row * DIM + tid];
        __syncthreads();
        float acc = bc;
        #pragma unroll
        for (int d = 0; d < DIM; d++) acc = fmaf(xrow[d], kx1s[d * 96 + tid], acc);
        g_embproj[(size_t)row * 96 + tid] = acc;
        __syncthreads();
    }
}

// ---------------------------------------------------------------------------
// Kernel B: fused GRU1 -> GRU2 -> GLU -> dense, persistent scan over T.
// 128 blocks x 128 threads. Each warp owns 2 batch elements (lane = unit).
// ---------------------------------------------------------------------------
__global__ void __launch_bounds__(128, 1) rnn_kernel(
    const int*   __restrict__ tokens,
    const float* __restrict__ kh1, const float* __restrict__ b1,
    const float* __restrict__ kx2, const float* __restrict__ kh2,
    const float* __restrict__ b2,
    const float* __restrict__ wg,  const float* __restrict__ bg,
    const float* __restrict__ wd,  const float* __restrict__ bd,
    float* __restrict__ out)
{
    extern __shared__ float smem[];
    float* kh1s = smem;                          // [32][97]
    float* kx2s = kh1s + NU1 * KH1_STRIDE;       // [32][193]
    float* kh2s = kx2s + NU1 * KX2_STRIDE;       // [64][193]
    float* bh1s = kh2s + NU2 * KH2_STRIDE;       // [96]   recurrent bias GRU1
    float* b2xs = bh1s + 96;                     // [192]  input bias GRU2
    float* bh2s = b2xs + 192;                    // [192]  recurrent bias GRU2
    float* h1s  = bh2s + 192;                    // [4 warps][2 elems][32]
    float* h2s  = h1s + 4 * 2 * NU1;             // [4 warps][2 elems][64]

    const int tid = threadIdx.x;

    // --- stage weights into padded smem ---
    for (int i = tid; i < NU1 * 96;  i += 128) kh1s[(i / 96)  * KH1_STRIDE + (i % 96)]  = kh1[i];
    for (int i = tid; i < NU1 * 192; i += 128) kx2s[(i / 192) * KX2_STRIDE + (i % 192)] = kx2[i];
    for (int i = tid; i < NU2 * 192; i += 128) kh2s[(i / 192) * KH2_STRIDE + (i % 192)] = kh2[i];
    for (int i = tid; i < 96;  i += 128) bh1s[i] = b1[96 + i];
    for (int i = tid; i < 192; i += 128) { b2xs[i] = b2[i]; bh2s[i] = b2[192 + i]; }
    for (int i = tid; i < 4 * 2 * NU1; i += 128) h1s[i] = 0.0f;
    for (int i = tid; i < 4 * 2 * NU2; i += 128) h2s[i] = 0.0f;
    __syncthreads();

    const int wid = tid >> 5;
    const int l   = tid & 31;
    const int e0  = blockIdx.x * 8 + wid * 2;   // exactly covers 0..1023
    const int e1  = e0 + 1;
    float* h1w = h1s + wid * (2 * NU1);
    float* h2w = h2s + wid * (2 * NU2);

    const int* tok0 = tokens + (size_t)e0 * NT;
    const int* tok1 = tokens + (size_t)e1 * NT;

    // register-cached biases
    const float bz1 = bh1s[l], br1 = bh1s[32 + l], bg1 = bh1s[64 + l];
    // GRU2 column set for this lane: {z_l, z_{l+32}, r_l, r_{l+32}, h_l, h_{l+32}}
    float initA[6], initH[2];
    {
        const int c[6] = { l, l + 32, 64 + l, 96 + l, 128 + l, 160 + l };
        #pragma unroll
        for (int k = 0; k < 6; k++)
            initA[k] = b2xs[c[k]] + (k < 4 ? bh2s[c[k]] : 0.0f);
        initH[0] = bh2s[c[4]];
        initH[1] = bh2s[c[5]];
    }

    float h1o0 = 0.0f, h1o1 = 0.0f;                        // lane-owned GRU1 unit l
    float h2o00 = 0.0f, h2o01 = 0.0f;                      // e0: units l, l+32
    float h2o10 = 0.0f, h2o11 = 0.0f;                      // e1: units l, l+32

    int tk0 = 0, tk1 = 0;  // 32-token register chunks

    for (int t = 0; t < NT; t++) {
        if ((t & 31) == 0) { tk0 = tok0[t + l]; tk1 = tok1[t + l]; }
        const int ti0 = __shfl_sync(0xffffffffu, tk0, t & 31);
        const int ti1 = __shfl_sync(0xffffffffu, tk1, t & 31);
        // issue xproj1 gathers early (L2 hits) -- consumed after GRU1 j-loop
        const float* ep0 = g_embproj + (size_t)ti0 * 96;
        const float* ep1 = g_embproj + (size_t)ti1 * 96;
        const float xz0 = __ldg(ep0 + l), xr0 = __ldg(ep0 + 32 + l), xh0 = __ldg(ep0 + 64 + l);
        const float xz1 = __ldg(ep1 + l), xr1 = __ldg(ep1 + 32 + l), xh1 = __ldg(ep1 + 64 + l);

        // ---------------- GRU1 recurrent: hm = h1 @ kh1 + bh1 ----------------
        float az0 = bz1, ar0 = br1, ah0 = bg1;
        float az1 = bz1, ar1 = br1, ah1 = bg1;
        #pragma unroll 4
        for (int j = 0; j < NU1; j += 4) {
            const float4 hA = *(const float4*)(h1w + j);
            const float4 hB = *(const float4*)(h1w + NU1 + j);
            #pragma unroll
            for (int jj = 0; jj < 4; jj++) {
                const float* wr = kh1s + (j + jj) * KH1_STRIDE;
                const float w0 = wr[l], w1 = wr[32 + l], w2 = wr[64 + l];
                const float va = (&hA.x)[jj], vb = (&hB.x)[jj];
                az0 = fmaf(w0, va, az0); ar0 = fmaf(w1, va, ar0); ah0 = fmaf(w2, va, ah0);
                az1 = fmaf(w0, vb, az1); ar1 = fmaf(w1, vb, ar1); ah1 = fmaf(w2, vb, ah1);
            }
        }
        {
            const float z = sigf(xz0 + az0), r = sigf(xr0 + ar0);
            const float hh = tanh_fast(xh0 + r * ah0);
            h1o0 = z * h1o0 + (1.0f - z) * hh;
        }
        {
            const float z = sigf(xz1 + az1), r = sigf(xr1 + ar1);
            const float hh = tanh_fast(xh1 + r * ah1);
            h1o1 = z * h1o1 + (1.0f - z) * hh;
        }
        __syncwarp();
        h1w[l]       = h1o0;
        h1w[NU1 + l] = h1o1;
        __syncwarp();

        // ---------------- GRU2: xt = h1@kx2 + b2[0], hm = h2@kh2 + b2[1] ----
        float a0[6], a1[6], hx0[2], hx1[2];
        #pragma unroll
        for (int k = 0; k < 6; k++) { a0[k] = initA[k]; a1[k] = initA[k]; }
        hx0[0] = initH[0]; hx0[1] = initH[1];
        hx1[0] = initH[0]; hx1[1] = initH[1];

        // input projection (reads NEW h1)
        #pragma unroll 4
        for (int j = 0; j < NU1; j += 4) {
            const float4 hA = *(const float4*)(h1w + j);
            const float4 hB = *(const float4*)(h1w + NU1 + j);
            #pragma unroll
            for (int jj = 0; jj < 4; jj++) {
                const float* wr = kx2s + (j + jj) * KX2_STRIDE;
                const float w0 = wr[l],       w1 = wr[32 + l],  w2 = wr[64 + l];
                const float w3 = wr[96 + l],  w4 = wr[128 + l], w5 = wr[160 + l];
                const float va = (&hA.x)[jj], vb = (&hB.x)[jj];
                a0[0] = fmaf(w0, va, a0[0]); a0[1] = fmaf(w1, va, a0[1]);
                a0[2] = fmaf(w2, va, a0[2]); a0[3] = fmaf(w3, va, a0[3]);
                a0[4] = fmaf(w4, va, a0[4]); a0[5] = fmaf(w5, va, a0[5]);
                a1[0] = fmaf(w0, vb, a1[0]); a1[1] = fmaf(w1, vb, a1[1]);
                a1[2] = fmaf(w2, vb, a1[2]); a1[3] = fmaf(w3, vb, a1[3]);
                a1[4] = fmaf(w4, vb, a1[4]); a1[5] = fmaf(w5, vb, a1[5]);
            }
        }
        // recurrent part (reads OLD h2); h-gate recurrent term kept separate
        #pragma unroll 4
        for (int j = 0; j < NU2; j += 4) {
            const float4 hA = *(const float4*)(h2w + j);
            const float4 hB = *(const float4*)(h2w + NU2 + j);
            #pragma unroll
            for (int jj = 0; jj < 4; jj++) {
                const float* wr = kh2s + (j + jj) * KH2_STRIDE;
                const float w0 = wr[l],       w1 = wr[32 + l],  w2 = wr[64 + l];
                const float w3 = wr[96 + l],  w4 = wr[128 + l], w5 = wr[160 + l];
                const float va = (&hA.x)[jj], vb = (&hB.x)[jj];
                a0[0] = fmaf(w0, va, a0[0]); a0[1] = fmaf(w1, va, a0[1]);
                a0[2] = fmaf(w2, va, a0[2]); a0[3] = fmaf(w3, va, a0[3]);
                hx0[0] = fmaf(w4, va, hx0[0]); hx0[1] = fmaf(w5, va, hx0[1]);
                a1[0] = fmaf(w0, vb, a1[0]); a1[1] = fmaf(w1, vb, a1[1]);
                a1[2] = fmaf(w2, vb, a1[2]); a1[3] = fmaf(w3, vb, a1[3]);
                hx1[0] = fmaf(w4, vb, hx1[0]); hx1[1] = fmaf(w5, vb, hx1[1]);
            }
        }
        // gates: unit l -> (a[0], a[2], a[4]+hx[0]); unit l+32 -> (a[1], a[3], a[5]+hx[1])
        {
            float z = sigf(a0[0]), r = sigf(a0[2]);
            float hh = tanh_fast(a0[4] + r * hx0[0]);
            h2o00 = z * h2o00 + (1.0f - z) * hh;
            z = sigf(a0[1]); r = sigf(a0[3]);
            hh = tanh_fast(a0[5] + r * hx0[1]);
            h2o01 = z * h2o01 + (1.0f - z) * hh;
        }
        {
            float z = sigf(a1[0]), r = sigf(a1[2]);
            float hh = tanh_fast(a1[4] + r * hx1[0]);
            h2o10 = z * h2o10 + (1.0f - z) * hh;
            z = sigf(a1[1]); r = sigf(a1[3]);
            hh = tanh_fast(a1[5] + r * hx1[1]);
            h2o11 = z * h2o11 + (1.0f - z) * hh;
        }
        __syncwarp();
        h2w[l]            = h2o00;
        h2w[32 + l]       = h2o01;
        h2w[NU2 + l]      = h2o10;
        h2w[NU2 + 32 + l] = h2o11;
        __syncwarp();
    }

    // ---------------- head: a = h2@wg + bg ; GLU ; sigmoid(x@wd + bd) -------
    #pragma unroll 1
    for (int e = 0; e < 2; e++) {
        const float* h2e = h2w + e * NU2;
        const int eg = (e == 0) ? e0 : e1;
        float acc[8];
        #pragma unroll
        for (int k = 0; k < 8; k++) acc[k] = __ldg(bg + l + 32 * k);
        for (int j = 0; j < NU2; j++) {
            const float hv = h2e[j];
            const float* wr = wg + j * 256 + l;
            #pragma unroll
            for (int k = 0; k < 8; k++) acc[k] = fmaf(hv, __ldg(wr + 32 * k), acc[k]);
        }
        float s = 0.0f;
        #pragma unroll
        for (int k = 0; k < 4; k++) {
            const float g = acc[k] * sigf(acc[k + 4]);   // GLU: a[i] * sig(a[i+128])
            s = fmaf(g, __ldg(wd + l + 32 * k), s);
        }
        #pragma unroll
        for (int off = 16; off >= 1; off >>= 1) s += __shfl_xor_sync(0xffffffffu, s, off);
        if (l == 0) out[eg] = sigf(s + __ldg(bd));
    }
}

// ---------------------------------------------------------------------------
extern "C" void kernel_launch(void* const* d_in, const int* in_sizes, int n_in,
                              void* d_out, int out_size) {
    const int*   tokens = (const int*)d_in[0];
    const float* emb = (const float*)d_in[1];
    const float* kx1 = (const float*)d_in[2];
    const float* kh1 = (const float*)d_in[3];
    const float* b1  = (const float*)d_in[4];
    const float* kx2 = (const float*)d_in[5];
    const float* kh2 = (const float*)d_in[6];
    const float* b2  = (const float*)d_in[7];
    const float* wg  = (const float*)d_in[8];
    const float* bg  = (const float*)d_in[9];
    const float* wd  = (const float*)d_in[10];
    const float* bd  = (const float*)d_in[11];
    float* out = (float*)d_out;

    const size_t smem_bytes = (size_t)(NU1 * KH1_STRIDE + NU1 * KX2_STRIDE + NU2 * KH2_STRIDE
                                       + 96 + 192 + 192 + 4 * 2 * NU1 + 4 * 2 * NU2) * sizeof(float);
    cudaFuncSetAttribute(rnn_kernel, cudaFuncAttributeMaxDynamicSharedMemorySize, (int)smem_bytes);

    embproj_kernel<<<(VOCAB + 15) / 16, 96>>>(emb, kx1, b1);
    rnn_kernel<<<NB / 8, 128, smem_bytes>>>(tokens, kh1, b1, kx2, kh2, b2, wg, bg, wd, bd, out);
}

// round 2
// speedup vs baseline: 1.6841x; 1.6841x over previous
#include <cuda_runtime.h>

// Problem dims
constexpr int VOCAB = 50257;
constexpr int DIM   = 50;
constexpr int NU1   = 32;   // GRU1 units, 3*NU1 = 96
constexpr int NU2   = 64;   // GRU2 units, 3*NU2 = 192
constexpr int NB    = 1024;
constexpr int NT    = 1024;

constexpr int KH1_STRIDE = 97;   // pad 96 -> 97 so bank = (j + c) % 32 (conflict-free)
constexpr int KX2_STRIDE = 193;  // pad 192 -> 193
constexpr int KH2_STRIDE = 193;

// Precomputed embedding projection: embproj[v][k] = sum_d emb[v][d]*kx1[d][k] + b1[0][k]
// 50257 * 96 floats = 19.3 MB -> lives in L2 during the recurrent kernel.
__device__ float g_embproj[(size_t)VOCAB * 96];

__device__ __forceinline__ float sigf(float x) {
    return __fdividef(1.0f, 1.0f + __expf(-x));
}
__device__ __forceinline__ float tanh_fast(float x) {
    // tanh(x) = 1 - 2/(exp(2x)+1); saturates correctly at +-inf
    return 1.0f - __fdividef(2.0f, 1.0f + __expf(2.0f * x));
}

// ---------------------------------------------------------------------------
// Kernel A: embproj = emb @ kx1 + b1[0]   ([V,50] x [50,96] -> [V,96])
// ---------------------------------------------------------------------------
__global__ void __launch_bounds__(96) embproj_kernel(const float* __restrict__ emb,
                                                     const float* __restrict__ kx1,
                                                     const float* __restrict__ b1) {
    __shared__ float kx1s[DIM * 96];
    __shared__ float xrow[DIM];
    const int tid = threadIdx.x;  // 96 threads, one per output column
    for (int i = tid; i < DIM * 96; i += 96) kx1s[i] = kx1[i];
    const float bc = b1[tid];  // b1[0][tid]
    __syncthreads();

    const int row0 = blockIdx.x * 16;
    for (int k = 0; k < 16; k++) {
        const int row = row0 + k;
        if (row >= VOCAB) break;
        if (tid < DIM) xrow[tid] = emb[(size_t)row * DIM + tid];
        __syncthreads();
        float acc = bc;
        #pragma unroll
        for (int d = 0; d < DIM; d++) acc = fmaf(xrow[d], kx1s[d * 96 + tid], acc);
        g_embproj[(size_t)row * 96 + tid] = acc;
        __syncthreads();
    }
}

// ---------------------------------------------------------------------------
// Kernel B: fused GRU1 -> GRU2 -> GLU -> dense, persistent scan over T.
// 128 blocks x 128 threads. Each warp owns 2 batch elements (lane = unit).
// ---------------------------------------------------------------------------
__global__ void __launch_bounds__(128, 1) rnn_kernel(
    const int*   __restrict__ tokens,
    const float* __restrict__ kh1, const float* __restrict__ b1,
    const float* __restrict__ kx2, const float* __restrict__ kh2,
    const float* __restrict__ b2,
    const float* __restrict__ wg,  const float* __restrict__ bg,
    const float* __restrict__ wd,  const float* __restrict__ bd,
    float* __restrict__ out)
{
    extern __shared__ float smem[];
    float* kh1s = smem;                          // [32][97]
    float* kx2s = kh1s + NU1 * KH1_STRIDE;       // [32][193]
    float* kh2s = kx2s + NU1 * KX2_STRIDE;       // [64][193]
    float* bh1s = kh2s + NU2 * KH2_STRIDE;       // [96]   recurrent bias GRU1
    float* b2xs = bh1s + 96;                     // [192]  input bias GRU2
    float* bh2s = b2xs + 192;                    // [192]  recurrent bias GRU2
    float* h1s  = bh2s + 192;                    // [4 warps][2 elems][32]
    float* h2s  = h1s + 4 * 2 * NU1;             // [4 warps][2 elems][64]

    const int tid = threadIdx.x;

    // --- stage weights into padded smem ---
    for (int i = tid; i < NU1 * 96;  i += 128) kh1s[(i / 96)  * KH1_STRIDE + (i % 96)]  = kh1[i];
    for (int i = tid; i < NU1 * 192; i += 128) kx2s[(i / 192) * KX2_STRIDE + (i % 192)] = kx2[i];
    for (int i = tid; i < NU2 * 192; i += 128) kh2s[(i / 192) * KH2_STRIDE + (i % 192)] = kh2[i];
    for (int i = tid; i < 96;  i += 128) bh1s[i] = b1[96 + i];
    for (int i = tid; i < 192; i += 128) { b2xs[i] = b2[i]; bh2s[i] = b2[192 + i]; }
    for (int i = tid; i < 4 * 2 * NU1; i += 128) h1s[i] = 0.0f;
    for (int i = tid; i < 4 * 2 * NU2; i += 128) h2s[i] = 0.0f;
    __syncthreads();

    const int wid = tid >> 5;
    const int l   = tid & 31;
    const int e0  = blockIdx.x * 8 + wid * 2;   // exactly covers 0..1023
    const int e1  = e0 + 1;
    float* h1w = h1s + wid * (2 * NU1);
    float* h2w = h2s + wid * (2 * NU2);

    const int* tok0 = tokens + (size_t)e0 * NT;
    const int* tok1 = tokens + (size_t)e1 * NT;

    // register-cached biases
    const float bz1 = bh1s[l], br1 = bh1s[32 + l], bg1 = bh1s[64 + l];
    // GRU2 column set for this lane: {z_l, z_{l+32}, r_l, r_{l+32}, h_l, h_{l+32}}
    float initA[6], initH[2];
    {
        const int c[6] = { l, l + 32, 64 + l, 96 + l, 128 + l, 160 + l };
        #pragma unroll
        for (int k = 0; k < 6; k++)
            initA[k] = b2xs[c[k]] + (k < 4 ? bh2s[c[k]] : 0.0f);
        initH[0] = bh2s[c[4]];
        initH[1] = bh2s[c[5]];
    }

    float h1o0 = 0.0f, h1o1 = 0.0f;                        // lane-owned GRU1 unit l
    float h2o00 = 0.0f, h2o01 = 0.0f;                      // e0: units l, l+32
    float h2o10 = 0.0f, h2o11 = 0.0f;                      // e1: units l, l+32

    int tk0 = 0, tk1 = 0;  // 32-token register chunks

    for (int t = 0; t < NT; t++) {
        if ((t & 31) == 0) { tk0 = tok0[t + l]; tk1 = tok1[t + l]; }
        const int ti0 = __shfl_sync(0xffffffffu, tk0, t & 31);
        const int ti1 = __shfl_sync(0xffffffffu, tk1, t & 31);
        // issue xproj1 gathers early (L2 hits) -- consumed after GRU1 j-loop
        const float* ep0 = g_embproj + (size_t)ti0 * 96;
        const float* ep1 = g_embproj + (size_t)ti1 * 96;
        const float xz0 = __ldg(ep0 + l), xr0 = __ldg(ep0 + 32 + l), xh0 = __ldg(ep0 + 64 + l);
        const float xz1 = __ldg(ep1 + l), xr1 = __ldg(ep1 + 32 + l), xh1 = __ldg(ep1 + 64 + l);

        // ---------------- GRU1 recurrent: hm = h1 @ kh1 + bh1 ----------------
        float az0 = bz1, ar0 = br1, ah0 = bg1;
        float az1 = bz1, ar1 = br1, ah1 = bg1;
        #pragma unroll 4
        for (int j = 0; j < NU1; j += 4) {
            const float4 hA = *(const float4*)(h1w + j);
            const float4 hB = *(const float4*)(h1w + NU1 + j);
            #pragma unroll
            for (int jj = 0; jj < 4; jj++) {
                const float* wr = kh1s + (j + jj) * KH1_STRIDE;
                const float w0 = wr[l], w1 = wr[32 + l], w2 = wr[64 + l];
                const float va = (&hA.x)[jj], vb = (&hB.x)[jj];
                az0 = fmaf(w0, va, az0); ar0 = fmaf(w1, va, ar0); ah0 = fmaf(w2, va, ah0);
                az1 = fmaf(w0, vb, az1); ar1 = fmaf(w1, vb, ar1); ah1 = fmaf(w2, vb, ah1);
            }
        }
        {
            const float z = sigf(xz0 + az0), r = sigf(xr0 + ar0);
            const float hh = tanh_fast(xh0 + r * ah0);
            h1o0 = z * h1o0 + (1.0f - z) * hh;
        }
        {
            const float z = sigf(xz1 + az1), r = sigf(xr1 + ar1);
            const float hh = tanh_fast(xh1 + r * ah1);
            h1o1 = z * h1o1 + (1.0f - z) * hh;
        }
        __syncwarp();
        h1w[l]       = h1o0;
        h1w[NU1 + l] = h1o1;
        __syncwarp();

        // ---------------- GRU2: xt = h1@kx2 + b2[0], hm = h2@kh2 + b2[1] ----
        float a0[6], a1[6], hx0[2], hx1[2];
        #pragma unroll
        for (int k = 0; k < 6; k++) { a0[k] = initA[k]; a1[k] = initA[k]; }
        hx0[0] = initH[0]; hx0[1] = initH[1];
        hx1[0] = initH[0]; hx1[1] = initH[1];

        // input projection (reads NEW h1)
        #pragma unroll 4
        for (int j = 0; j < NU1; j += 4) {
            const float4 hA = *(const float4*)(h1w + j);
            const float4 hB = *(const float4*)(h1w + NU1 + j);
            #pragma unroll
            for (int jj = 0; jj < 4; jj++) {
                const float* wr = kx2s + (j + jj) * KX2_STRIDE;
                const float w0 = wr[l],       w1 = wr[32 + l],  w2 = wr[64 + l];
                const float w3 = wr[96 + l],  w4 = wr[128 + l], w5 = wr[160 + l];
                const float va = (&hA.x)[jj], vb = (&hB.x)[jj];
                a0[0] = fmaf(w0, va, a0[0]); a0[1] = fmaf(w1, va, a0[1]);
                a0[2] = fmaf(w2, va, a0[2]); a0[3] = fmaf(w3, va, a0[3]);
                a0[4] = fmaf(w4, va, a0[4]); a0[5] = fmaf(w5, va, a0[5]);
                a1[0] = fmaf(w0, vb, a1[0]); a1[1] = fmaf(w1, vb, a1[1]);
                a1[2] = fmaf(w2, vb, a1[2]); a1[3] = fmaf(w3, vb, a1[3]);
                a1[4] = fmaf(w4, vb, a1[4]); a1[5] = fmaf(w5, vb, a1[5]);
            }
        }
        // recurrent part (reads OLD h2); h-gate recurrent term kept separate
        #pragma unroll 4
        for (int j = 0; j < NU2; j += 4) {
            const float4 hA = *(const float4*)(h2w + j);
            const float4 hB = *(const float4*)(h2w + NU2 + j);
            #pragma unroll
            for (int jj = 0; jj < 4; jj++) {
                const float* wr = kh2s + (j + jj) * KH2_STRIDE;
                const float w0 = wr[l],       w1 = wr[32 + l],  w2 = wr[64 + l];
                const float w3 = wr[96 + l],  w4 = wr[128 + l], w5 = wr[160 + l];
                const float va = (&hA.x)[jj], vb = (&hB.x)[jj];
                a0[0] = fmaf(w0, va, a0[0]); a0[1] = fmaf(w1, va, a0[1]);
                a0[2] = fmaf(w2, va, a0[2]); a0[3] = fmaf(w3, va, a0[3]);
                hx0[0] = fmaf(w4, va, hx0[0]); hx0[1] = fmaf(w5, va, hx0[1]);
                a1[0] = fmaf(w0, vb, a1[0]); a1[1] = fmaf(w1, vb, a1[1]);
                a1[2] = fmaf(w2, vb, a1[2]); a1[3] = fmaf(w3, vb, a1[3]);
                hx1[0] = fmaf(w4, vb, hx1[0]); hx1[1] = fmaf(w5, vb, hx1[1]);
            }
        }
        // gates: unit l -> (a[0], a[2], a[4]+hx[0]); unit l+32 -> (a[1], a[3], a[5]+hx[1])
        {
            float z = sigf(a0[0]), r = sigf(a0[2]);
            float hh = tanh_fast(a0[4] + r * hx0[0]);
            h2o00 = z * h2o00 + (1.0f - z) * hh;
            z = sigf(a0[1]); r = sigf(a0[3]);
            hh = tanh_fast(a0[5] + r * hx0[1]);
            h2o01 = z * h2o01 + (1.0f - z) * hh;
        }
        {
            float z = sigf(a1[0]), r = sigf(a1[2]);
            float hh = tanh_fast(a1[4] + r * hx1[0]);
            h2o10 = z * h2o10 + (1.0f - z) * hh;
            z = sigf(a1[1]); r = sigf(a1[3]);
            hh = tanh_fast(a1[5] + r * hx1[1]);
            h2o11 = z * h2o11 + (1.0f - z) * hh;
        }
        __syncwarp();
        h2w[l]            = h2o00;
        h2w[32 + l]       = h2o01;
        h2w[NU2 + l]      = h2o10;
        h2w[NU2 + 32 + l] = h2o11;
        __syncwarp();
    }

    // ---------------- head: a = h2@wg + bg ; GLU ; sigmoid(x@wd + bd) -------
    #pragma unroll 1
    for (int e = 0; e < 2; e++) {
        const float* h2e = h2w + e * NU2;
        const int eg = (e == 0) ? e0 : e1;
        float acc[8];
        #pragma unroll
        for (int k = 0; k < 8; k++) acc[k] = __ldg(bg + l + 32 * k);
        for (int j = 0; j < NU2; j++) {
            const float hv = h2e[j];
            const float* wr = wg + j * 256 + l;
            #pragma unroll
            for (int k = 0; k < 8; k++) acc[k] = fmaf(hv, __ldg(wr + 32 * k), acc[k]);
        }
        float s = 0.0f;
        #pragma unroll
        for (int k = 0; k < 4; k++) {
            const float g = acc[k] * sigf(acc[k + 4]);   // GLU: a[i] * sig(a[i+128])
            s = fmaf(g, __ldg(wd + l + 32 * k), s);
        }
        #pragma unroll
        for (int off = 16; off >= 1; off >>= 1) s += __shfl_xor_sync(0xffffffffu, s, off);
        if (l == 0) out[eg] = sigf(s + __ldg(bd));
    }
}

// ---------------------------------------------------------------------------
extern "C" void kernel_launch(void* const* d_in, const int* in_sizes, int n_in,
                              void* d_out, int out_size) {
    const int*   tokens = (const int*)d_in[0];
    const float* emb = (const float*)d_in[1];
    const float* kx1 = (const float*)d_in[2];
    const float* kh1 = (const float*)d_in[3];
    const float* b1  = (const float*)d_in[4];
    const float* kx2 = (const float*)d_in[5];
    const float* kh2 = (const float*)d_in[6];
    const float* b2  = (const float*)d_in[7];
    const float* wg  = (const float*)d_in[8];
    const float* bg  = (const float*)d_in[9];
    const float* wd  = (const float*)d_in[10];
    const float* bd  = (const float*)d_in[11];
    float* out = (float*)d_out;

    const size_t smem_bytes = (size_t)(NU1 * KH1_STRIDE + NU1 * KX2_STRIDE + NU2 * KH2_STRIDE
                                       + 96 + 192 + 192 + 4 * 2 * NU1 + 4 * 2 * NU2) * sizeof(float);
    cudaFuncSetAttribute(rnn_kernel, cudaFuncAttributeMaxDynamicSharedMemorySize, (int)smem_bytes);

    embproj_kernel<<<(VOCAB + 15) / 16, 96>>>(emb, kx1, b1);
    rnn_kernel<<<NB / 8, 128, smem_bytes>>>(tokens, kh1, b1, kx2, kh2, b2, wg, bg, wd, bd, out);
}

// round 3
// speedup vs baseline: 1.9335x; 1.1481x over previous
#include <cuda_runtime.h>

constexpr int VOCAB = 50257;
constexpr int DIM   = 50;
constexpr int NU1   = 32;
constexpr int NU2   = 64;
constexpr int NB    = 1024;
constexpr int NT    = 1024;

using u64 = unsigned long long;

// Precomputed embedding projection: embproj[v][k] = emb[v]@kx1[:,k] + b1[0][k]
// 50257*96 floats = 19.3 MB -> L2 resident during the recurrent kernel.
__device__ float g_embproj[(size_t)VOCAB * 96];

__device__ __forceinline__ u64 pack2(float lo, float hi) {
    u64 r; asm("mov.b64 %0, {%1, %2};" : "=l"(r) : "f"(lo), "f"(hi)); return r;
}
__device__ __forceinline__ u64 dup2(float v) { return pack2(v, v); }
__device__ __forceinline__ void unpack2(u64 p, float& lo, float& hi) {
    asm("mov.b64 {%0, %1}, %2;" : "=f"(lo), "=f"(hi) : "l"(p));
}
__device__ __forceinline__ u64 fma2(u64 a, u64 b, u64 c) {
    u64 d; asm("fma.rn.f32x2 %0, %1, %2, %3;" : "=l"(d) : "l"(a), "l"(b), "l"(c)); return d;
}
__device__ __forceinline__ u64 add2(u64 a, u64 b) {
    u64 d; asm("add.rn.f32x2 %0, %1, %2;" : "=l"(d) : "l"(a), "l"(b)); return d;
}
__device__ __forceinline__ float sigf(float x) {
    return __fdividef(1.0f, 1.0f + __expf(-x));
}
__device__ __forceinline__ float tanh_fast(float x) {
    return 1.0f - __fdividef(2.0f, 1.0f + __expf(2.0f * x));
}

// ---------------------------------------------------------------------------
// Kernel A: embproj = emb @ kx1 + b1[0]
// ---------------------------------------------------------------------------
__global__ void __launch_bounds__(96) embproj_kernel(const float* __restrict__ emb,
                                                     const float* __restrict__ kx1,
                                                     const float* __restrict__ b1) {
    __shared__ float kx1s[DIM * 96];
    __shared__ float xrow[DIM];
    const int tid = threadIdx.x;
    for (int i = tid; i < DIM * 96; i += 96) kx1s[i] = kx1[i];
    const float bc = b1[tid];
    __syncthreads();
    const int row0 = blockIdx.x * 16;
    for (int k = 0; k < 16; k++) {
        const int row = row0 + k;
        if (row >= VOCAB) break;
        if (tid < DIM) xrow[tid] = emb[(size_t)row * DIM + tid];
        __syncthreads();
        float acc = bc;
        #pragma unroll
        for (int d = 0; d < DIM; d++) acc = fmaf(xrow[d], kx1s[d * 96 + tid], acc);
        g_embproj[(size_t)row * 96 + tid] = acc;
        __syncthreads();
    }
}

// ---------------------------------------------------------------------------
// Kernel B: fused GRU1 -> GRU2 -> GLU -> dense.
// 128 blocks x 128 threads; block owns 8 batch elements; warp owns 2.
// kh2 lives in registers, j-split 4 ways across warps (partials via smem).
// kh1/kx2 in smem as gate-paired float2 for LDS.64 + FFMA2.
//
// smem map (floats):
//   [0,2048)      kh1zr  float2[32][32]  {kh1[j][c], kh1[j][32+c]}
//   [2048,3072)   kh1h   float [32][32]  kh1[j][64+c]
//   [3072,9216)   kx2p   u64   [32][3][32] {kx2[j][64g+c], kx2[j][64g+32+c]}
//   [9216,15360)  part   u64   [8][4][3][32] rec2 partials
//   [15360,15616) h1s    float [4][2][32]
//   [15616,16128) h2s    float [8][64]
// ---------------------------------------------------------------------------
constexpr int SMEM_FLOATS = 16128;

__global__ void __launch_bounds__(128, 1) rnn_kernel(
    const int*   __restrict__ tokens,
    const float* __restrict__ kh1, const float* __restrict__ b1,
    const float* __restrict__ kx2, const float* __restrict__ kh2,
    const float* __restrict__ b2,
    const float* __restrict__ wg,  const float* __restrict__ bg,
    const float* __restrict__ wd,  const float* __restrict__ bd,
    float* __restrict__ out)
{
    extern __shared__ float smem[];
    float2* kh1zr = (float2*)smem;            // [32][32]
    float*  kh1h  = smem + 2048;              // [32][32]
    u64*    kx2p  = (u64*)(smem + 3072);      // [32][3][32]
    u64*    part  = (u64*)(smem + 9216);      // [8][4][3][32]
    float*  h1s   = smem + 15360;             // [4][2][32]
    float*  h2s   = smem + 15616;             // [8][64]

    const int tid = threadIdx.x;

    // --- stage kh1 / kx2 into paired smem layouts ---
    for (int i = tid; i < 1024; i += 128) {
        const int j = i >> 5, c = i & 31;
        kh1zr[i] = make_float2(kh1[j * 96 + c], kh1[j * 96 + 32 + c]);
        kh1h[i]  = kh1[j * 96 + 64 + c];
    }
    for (int i = tid; i < 3072; i += 128) {
        const int j = i / 96, g = (i % 96) >> 5, c = i & 31;
        ((float2*)kx2p)[i] = make_float2(kx2[j * 192 + g * 64 + c],
                                         kx2[j * 192 + g * 64 + 32 + c]);
    }
    for (int i = tid; i < 256; i += 128) h1s[i] = 0.0f;
    for (int i = tid; i < 512; i += 128) h2s[i] = 0.0f;
    __syncthreads();

    const int wid = tid >> 5;
    const int l   = tid & 31;

    // --- kh2 quarter -> registers: rows [wid*16, wid*16+16), lane-paired cols ---
    u64 wz[16], wr[16], wh[16];
    {
        const float* base = kh2 + (size_t)(wid * 16) * 192;
        #pragma unroll
        for (int jj = 0; jj < 16; jj++) {
            const float* r = base + jj * 192;
            wz[jj] = pack2(__ldg(r + l),       __ldg(r + 32 + l));
            wr[jj] = pack2(__ldg(r + 64 + l),  __ldg(r + 96 + l));
            wh[jj] = pack2(__ldg(r + 128 + l), __ldg(r + 160 + l));
        }
    }

    // --- bias constants ---
    const u64 azr1b = pack2(__ldg(b1 + 96 + l), __ldg(b1 + 128 + l));   // GRU1 z,r rec bias
    const float bg1 = __ldg(b1 + 160 + l);                              // GRU1 h rec bias
    const u64 az4b = pack2(__ldg(b2 + l)        + __ldg(b2 + 192 + l),
                           __ldg(b2 + 32 + l)   + __ldg(b2 + 224 + l)); // z: bx+bh
    const u64 ar4b = pack2(__ldg(b2 + 64 + l)   + __ldg(b2 + 256 + l),
                           __ldg(b2 + 96 + l)   + __ldg(b2 + 288 + l)); // r: bx+bh
    const u64 axhb = pack2(__ldg(b2 + 128 + l), __ldg(b2 + 160 + l));   // h input bias
    const u64 bh2hp = pack2(__ldg(b2 + 320 + l), __ldg(b2 + 352 + l));  // h rec bias

    const int el0 = wid * 2;                 // local elems owned by this warp
    const int e0g = blockIdx.x * 8 + el0;
    const int e1g = e0g + 1;
    float* h1w = h1s + wid * 64;             // [2][32]

    const int* tok0 = tokens + (size_t)e0g * NT;
    const int* tok1 = tokens + (size_t)e1g * NT;

    float h1o0 = 0.0f, h1o1 = 0.0f;
    float h2a0 = 0.0f, h2b0 = 0.0f;          // e0: units l, l+32
    float h2a1 = 0.0f, h2b1 = 0.0f;          // e1

    int tk0 = 0, tk1 = 0;

    for (int t = 0; t < NT; t++) {
        // token fetch + embproj gather issued early (L2 resident)
        if ((t & 31) == 0) { tk0 = tok0[t + l]; tk1 = tok1[t + l]; }
        const int ti0 = __shfl_sync(0xffffffffu, tk0, t & 31);
        const int ti1 = __shfl_sync(0xffffffffu, tk1, t & 31);
        const float* ep0 = g_embproj + (size_t)ti0 * 96;
        const float* ep1 = g_embproj + (size_t)ti1 * 96;
        const float xz0 = __ldg(ep0 + l), xr0 = __ldg(ep0 + 32 + l), xh0 = __ldg(ep0 + 64 + l);
        const float xz1 = __ldg(ep1 + l), xr1 = __ldg(ep1 + 32 + l), xh1 = __ldg(ep1 + 64 + l);

        // ============ Stage 1: rec2 partials (old h2), all 8 elems ==========
        #pragma unroll 1
        for (int e = 0; e < 8; e++) {
            const float4* hv = (const float4*)(h2s + e * 64 + wid * 16);
            u64 az = 0ull, ar = 0ull, ah = 0ull;
            #pragma unroll
            for (int g4 = 0; g4 < 4; g4++) {
                const float4 v = hv[g4];
                u64 d;
                d = dup2(v.x); az = fma2(wz[g4*4+0], d, az); ar = fma2(wr[g4*4+0], d, ar); ah = fma2(wh[g4*4+0], d, ah);
                d = dup2(v.y); az = fma2(wz[g4*4+1], d, az); ar = fma2(wr[g4*4+1], d, ar); ah = fma2(wh[g4*4+1], d, ah);
                d = dup2(v.z); az = fma2(wz[g4*4+2], d, az); ar = fma2(wr[g4*4+2], d, ar); ah = fma2(wh[g4*4+2], d, ah);
                d = dup2(v.w); az = fma2(wz[g4*4+3], d, az); ar = fma2(wr[g4*4+3], d, ar); ah = fma2(wh[g4*4+3], d, ah);
            }
            u64* pb = part + (size_t)((e * 4 + wid) * 3) * 32 + l;
            pb[0] = az; pb[32] = ar; pb[64] = ah;
        }
        __syncthreads();   // partials visible; h2s reads done before stage-5 writes

        // ============ Stage 3: GRU1 (own 2 elems, smem kh1 paired) ==========
        u64 azr0 = azr1b, azr1 = azr1b;
        float ah0 = bg1, ah1 = bg1;
        {
            const float4* hA4 = (const float4*)h1w;
            const float4* hB4 = (const float4*)(h1w + 32);
            #pragma unroll
            for (int j4 = 0; j4 < 8; j4++) {
                const float4 hA = hA4[j4];
                const float4 hB = hB4[j4];
                #pragma unroll
                for (int jj = 0; jj < 4; jj++) {
                    const int j = j4 * 4 + jj;
                    const u64 wzr   = ((const u64*)kh1zr)[j * 32 + l];
                    const float whv = kh1h[j * 32 + l];
                    const float va = (&hA.x)[jj], vb = (&hB.x)[jj];
                    azr0 = fma2(wzr, dup2(va), azr0); ah0 = fmaf(whv, va, ah0);
                    azr1 = fma2(wzr, dup2(vb), azr1); ah1 = fmaf(whv, vb, ah1);
                }
            }
        }
        {
            float az, ar; unpack2(azr0, az, ar);
            const float z = sigf(xz0 + az), r = sigf(xr0 + ar);
            const float hh = tanh_fast(xh0 + r * ah0);
            h1o0 = z * h1o0 + (1.0f - z) * hh;
        }
        {
            float az, ar; unpack2(azr1, az, ar);
            const float z = sigf(xz1 + az), r = sigf(xr1 + ar);
            const float hh = tanh_fast(xh1 + r * ah1);
            h1o1 = z * h1o1 + (1.0f - z) * hh;
        }
        __syncwarp();
        h1w[l] = h1o0; h1w[32 + l] = h1o1;
        __syncwarp();

        // ============ Stage 4: xproj2 (own 2 elems, smem kx2 paired) ========
        u64 az40 = az4b, ar40 = ar4b, ax40 = axhb;
        u64 az41 = az4b, ar41 = ar4b, ax41 = axhb;
        {
            const float4* hA4 = (const float4*)h1w;
            const float4* hB4 = (const float4*)(h1w + 32);
            #pragma unroll
            for (int j4 = 0; j4 < 8; j4++) {
                const float4 hA = hA4[j4];
                const float4 hB = hB4[j4];
                #pragma unroll
                for (int jj = 0; jj < 4; jj++) {
                    const int j = j4 * 4 + jj;
                    const u64* wp = kx2p + (size_t)(j * 3) * 32 + l;
                    const u64 w0 = wp[0], w1 = wp[32], w2 = wp[64];
                    const u64 da = dup2((&hA.x)[jj]);
                    const u64 db = dup2((&hB.x)[jj]);
                    az40 = fma2(w0, da, az40); ar40 = fma2(w1, da, ar40); ax40 = fma2(w2, da, ax40);
                    az41 = fma2(w0, db, az41); ar41 = fma2(w1, db, ar41); ax41 = fma2(w2, db, ax41);
                }
            }
        }

        // ============ Stage 5: combine partials, GRU2 gates, update h2 ======
        #pragma unroll
        for (int e = 0; e < 2; e++) {
            const int el = el0 + e;
            u64 zp = (e == 0) ? az40 : az41;
            u64 rp = (e == 0) ? ar40 : ar41;
            u64 xp = (e == 0) ? ax40 : ax41;
            u64 hm = bh2hp;
            #pragma unroll
            for (int w = 0; w < 4; w++) {
                const u64* pb = part + (size_t)((el * 4 + w) * 3) * 32 + l;
                zp = add2(zp, pb[0]); rp = add2(rp, pb[32]); hm = add2(hm, pb[64]);
            }
            float zl, zh, rl, rh, hml, hmh, xl, xh;
            unpack2(zp, zl, zh); unpack2(rp, rl, rh);
            unpack2(hm, hml, hmh); unpack2(xp, xl, xh);
            float& ha = (e == 0) ? h2a0 : h2a1;
            float& hb = (e == 0) ? h2b0 : h2b1;
            {
                const float z = sigf(zl), r = sigf(rl);
                const float hh = tanh_fast(xl + r * hml);
                ha = z * ha + (1.0f - z) * hh;
            }
            {
                const float z = sigf(zh), r = sigf(rh);
                const float hh = tanh_fast(xh + r * hmh);
                hb = z * hb + (1.0f - z) * hh;
            }
            h2s[el * 64 + l]      = ha;
            h2s[el * 64 + 32 + l] = hb;
        }
        __syncthreads();   // h2 published; partial-buffer reads complete
    }

    // ---------------- head: a = h2@wg + bg ; GLU ; sigmoid(x@wd + bd) -------
    #pragma unroll 1
    for (int e = 0; e < 2; e++) {
        const float* h2e = h2s + (el0 + e) * 64;
        const int eg = (e == 0) ? e0g : e1g;
        float acc[8];
        #pragma unroll
        for (int k = 0; k < 8; k++) acc[k] = __ldg(bg + l + 32 * k);
        for (int j = 0; j < NU2; j++) {
            const float hv = h2e[j];
            const float* wrp = wg + j * 256 + l;
            #pragma unroll
            for (int k = 0; k < 8; k++) acc[k] = fmaf(hv, __ldg(wrp + 32 * k), acc[k]);
        }
        float s = 0.0f;
        #pragma unroll
        for (int k = 0; k < 4; k++) {
            const float g = acc[k] * sigf(acc[k + 4]);
            s = fmaf(g, __ldg(wd + l + 32 * k), s);
        }
        #pragma unroll
        for (int off = 16; off >= 1; off >>= 1) s += __shfl_xor_sync(0xffffffffu, s, off);
        if (l == 0) out[eg] = sigf(s + __ldg(bd));
    }
}

// ---------------------------------------------------------------------------
extern "C" void kernel_launch(void* const* d_in, const int* in_sizes, int n_in,
                              void* d_out, int out_size) {
    const int*   tokens = (const int*)d_in[0];
    const float* emb = (const float*)d_in[1];
    const float* kx1 = (const float*)d_in[2];
    const float* kh1 = (const float*)d_in[3];
    const float* b1  = (const float*)d_in[4];
    const float* kx2 = (const float*)d_in[5];
    const float* kh2 = (const float*)d_in[6];
    const float* b2  = (const float*)d_in[7];
    const float* wg  = (const float*)d_in[8];
    const float* bg  = (const float*)d_in[9];
    const float* wd  = (const float*)d_in[10];
    const float* bd  = (const float*)d_in[11];
    float* out = (float*)d_out;

    const size_t smem_bytes = SMEM_FLOATS * sizeof(float);
    cudaFuncSetAttribute(rnn_kernel, cudaFuncAttributeMaxDynamicSharedMemorySize, (int)smem_bytes);

    embproj_kernel<<<(VOCAB + 15) / 16, 96>>>(emb, kx1, b1);
    rnn_kernel<<<NB / 8, 128, smem_bytes>>>(tokens, kh1, b1, kx2, kh2, b2, wg, bg, wd, bd, out);
}